// round 1
// baseline (speedup 1.0000x reference)
#include <cuda_runtime.h>
#include <math.h>

#define Bn 32
#define Ln 2048
#define Dn 1024
#define Un 512

#define TM 128
#define TN 64
#define KC 32

// scratch (static device globals; no runtime allocation)
__device__ float g_ubias[Bn * Un];   // per (b,u) fused l-independent bias
__device__ float g_score[Bn * Ln];   // pre-softmax scores

__device__ __forceinline__ unsigned f2tf32(float f) {
    unsigned u;
    asm("cvt.rna.tf32.f32 %0, %1;" : "=r"(u) : "f"(f));
    return u;
}

// ---------------------------------------------------------------------------
// Kernel 1: per-batch prep.
//   inlen_b   = 1 + #zeros(mask[b,:])
//   g_ubias[b][u] = q[b]·Wh[:,u] + bh + bv + bp + bm
//                 + log(1+timestep)*Wp[0][u] + log(inlen_b)*Wp[2][u]
// ---------------------------------------------------------------------------
__global__ void prep_kernel(const float* __restrict__ query,
                            const float* __restrict__ mask,
                            const int*   __restrict__ tstep,
                            const float* __restrict__ Wh,
                            const float* __restrict__ bh,
                            const float* __restrict__ bv,
                            const float* __restrict__ Wp,
                            const float* __restrict__ bp,
                            const float* __restrict__ bm)
{
    int b = blockIdx.x;
    int tid = threadIdx.x;                 // 512 threads
    __shared__ float qs[Dn];
    __shared__ float red[512];
    __shared__ float s_loglen, s_logts;

    // count zeros in mask[b,:,0]
    float cnt = 0.f;
    for (int l = tid; l < Ln; l += 512)
        cnt += (mask[b * Ln + l] == 0.0f) ? 1.0f : 0.0f;
    red[tid] = cnt;
    __syncthreads();
    for (int s = 256; s > 0; s >>= 1) {
        if (tid < s) red[tid] += red[tid + s];
        __syncthreads();
    }
    if (tid == 0) {
        s_loglen = logf(1.0f + red[0]);
        // timestep dtype hedge: small int -> int32/int64 low word; else float bits
        int iv = tstep[0];
        float ts;
        if (iv >= 0 && iv < 1000000) ts = (float)iv;
        else ts = __int_as_float(iv);
        s_logts = logf(1.0f + ts);
    }
    for (int d = tid; d < Dn; d += 512) qs[d] = query[b * Dn + d];
    __syncthreads();

    int u = tid;  // 512 threads = Un
    float acc = 0.f;
#pragma unroll 8
    for (int d = 0; d < Dn; d++) acc += qs[d] * Wh[d * Un + u];
    g_ubias[b * Un + u] = acc + bh[u] + bv[u] + bp[u] + bm[u]
                        + s_logts * Wp[u] + s_loglen * Wp[2 * Un + u];
}

// ---------------------------------------------------------------------------
// Kernel 2: score init (vb + mask penalty) and zero the context output region
// ---------------------------------------------------------------------------
__global__ void init_kernel(const float* __restrict__ mask,
                            const float* __restrict__ vb,
                            float* __restrict__ out)
{
    int i = blockIdx.x * blockDim.x + threadIdx.x;
    if (i < Bn * Ln) g_score[i] = vb[0] + mask[i] * -1e9f;
    if (i < Bn * Dn) out[i] = 0.0f;  // context region
}

// ---------------------------------------------------------------------------
// Kernel 3: fused score GEMM (values @ Wv, tf32 tensor cores) + epilogue
//   Each block: TM=128 l-rows x TN=64 units, accumulate K=1024.
//   Epilogue: + ubias + log(2+l)*Wp1 + markov(prev window)·Wm, tanh, ·vw,
//   reduce over units, atomicAdd into g_score.
// ---------------------------------------------------------------------------
__global__ __launch_bounds__(256) void score_kernel(
    const float* __restrict__ values,
    const float* __restrict__ Wv,
    const float* __restrict__ Wp,
    const float* __restrict__ Wm,
    const float* __restrict__ vw,
    const float* __restrict__ prev)
{
    int utile = blockIdx.x;   // 8  (x-fastest: U-siblings share A-tile in L2)
    int ltile = blockIdx.y;   // 16
    int b     = blockIdx.z;   // 32
    int l0 = ltile * TM;
    int u0 = utile * TN;
    int tid = threadIdx.x;
    int lane = tid & 31, warp = tid >> 5;

    __shared__ unsigned As[TM * 33];   // [row][k] stride 33 (tf32 bits)
    __shared__ unsigned Bs[TN * 33];   // [n][k]   stride 33
    __shared__ float eb[TN * 8];       // ubias | wp1 | vw | wm[0..4]
    __shared__ float prevs[TM + 4];

    float c[8][4];
#pragma unroll
    for (int i = 0; i < 8; i++)
#pragma unroll
        for (int j = 0; j < 4; j++) c[i][j] = 0.f;

    const float* vbase = values + (size_t)b * Ln * Dn + (size_t)l0 * Dn;

    for (int kc = 0; kc < Dn; kc += KC) {
        __syncthreads();
        {   // A: 128x32, 16 elems/thread, coalesced over k
            int k  = tid & 31;
            int r0 = tid >> 5;       // 0..7
#pragma unroll
            for (int i = 0; i < 16; i++) {
                int row = r0 + i * 8;
                As[row * 33 + k] = f2tf32(vbase[(size_t)row * Dn + kc + k]);
            }
        }
        {   // B: 32x64 (k x n), 8 elems/thread, coalesced over n; stored [n][k]
            int n  = tid & 63;
            int k0 = tid >> 6;       // 0..3
#pragma unroll
            for (int i = 0; i < 8; i++) {
                int k = k0 + i * 4;
                Bs[n * 33 + k] = f2tf32(Wv[(size_t)(kc + k) * Un + u0 + n]);
            }
        }
        __syncthreads();

        int mr = warp * 16 + (lane >> 2);
#pragma unroll
        for (int k8 = 0; k8 < KC; k8 += 8) {
            unsigned a0 = As[mr * 33 + k8 + (lane & 3)];
            unsigned a1 = As[(mr + 8) * 33 + k8 + (lane & 3)];
            unsigned a2 = As[mr * 33 + k8 + 4 + (lane & 3)];
            unsigned a3 = As[(mr + 8) * 33 + k8 + 4 + (lane & 3)];
#pragma unroll
            for (int nt = 0; nt < 8; nt++) {
                unsigned b0 = Bs[(nt * 8 + (lane >> 2)) * 33 + k8 + (lane & 3)];
                unsigned b1 = Bs[(nt * 8 + (lane >> 2)) * 33 + k8 + 4 + (lane & 3)];
                asm volatile(
                    "mma.sync.aligned.m16n8k8.row.col.f32.tf32.tf32.f32 "
                    "{%0,%1,%2,%3}, {%4,%5,%6,%7}, {%8,%9}, {%0,%1,%2,%3};"
                    : "+f"(c[nt][0]), "+f"(c[nt][1]), "+f"(c[nt][2]), "+f"(c[nt][3])
                    : "r"(a0), "r"(a1), "r"(a2), "r"(a3), "r"(b0), "r"(b1));
            }
        }
    }

    // ---- epilogue staging ----
    __syncthreads();
    if (tid < TN) {
        int u = u0 + tid;
        eb[tid]        = g_ubias[b * Un + u];
        eb[64 + tid]   = Wp[Un + u];        // Wp[1][u]
        eb[128 + tid]  = vw[u];
#pragma unroll
        for (int j = 0; j < 5; j++) eb[192 + j * 64 + tid] = Wm[j * Un + u];
    }
    if (tid < TM + 4) {
        int gl = l0 - 2 + tid;
        prevs[tid] = (gl >= 0 && gl < Ln) ? prev[b * Ln + gl] : 0.0f;
    }
    __syncthreads();

    int mr = warp * 16 + (lane >> 2);
    float llA = logf(2.0f + (float)(l0 + mr));
    float llB = logf(2.0f + (float)(l0 + mr + 8));
    float sumA = 0.f, sumB = 0.f;
#pragma unroll
    for (int nt = 0; nt < 8; nt++) {
#pragma unroll
        for (int i = 0; i < 4; i++) {
            int col  = nt * 8 + (lane & 3) * 2 + (i & 1);
            int rloc = (i < 2) ? mr : mr + 8;
            float ll = (i < 2) ? llA : llB;
            float s = c[nt][i] + eb[col] + ll * eb[64 + col];
#pragma unroll
            for (int j = 0; j < 5; j++)
                s += prevs[rloc + j] * eb[192 + j * 64 + col];
            float t = tanhf(s) * eb[128 + col];
            if (i < 2) sumA += t; else sumB += t;
        }
    }
    // quad reduction: lanes differing in (lane&3) hold same rows
    sumA += __shfl_xor_sync(0xffffffffu, sumA, 1);
    sumA += __shfl_xor_sync(0xffffffffu, sumA, 2);
    sumB += __shfl_xor_sync(0xffffffffu, sumB, 1);
    sumB += __shfl_xor_sync(0xffffffffu, sumB, 2);
    if ((lane & 3) == 0) {
        atomicAdd(&g_score[b * Ln + l0 + mr], sumA);
        atomicAdd(&g_score[b * Ln + l0 + mr + 8], sumB);
    }
}

// ---------------------------------------------------------------------------
// Kernel 4: softmax over L per batch -> attention weights into d_out
// ---------------------------------------------------------------------------
__global__ void softmax_kernel(float* __restrict__ out)
{
    int b = blockIdx.x;
    int tid = threadIdx.x;   // 256
    __shared__ float red[256];
    __shared__ float s_max, s_inv;

    float m = -1e30f;
    for (int l = tid; l < Ln; l += 256) m = fmaxf(m, g_score[b * Ln + l]);
    red[tid] = m;
    __syncthreads();
    for (int s = 128; s > 0; s >>= 1) {
        if (tid < s) red[tid] = fmaxf(red[tid], red[tid + s]);
        __syncthreads();
    }
    if (tid == 0) s_max = red[0];
    __syncthreads();

    float sum = 0.f;
    for (int l = tid; l < Ln; l += 256) sum += expf(g_score[b * Ln + l] - s_max);
    red[tid] = sum;
    __syncthreads();
    for (int s = 128; s > 0; s >>= 1) {
        if (tid < s) red[tid] += red[tid + s];
        __syncthreads();
    }
    if (tid == 0) s_inv = 1.0f / red[0];
    __syncthreads();

    float* attn = out + Bn * Dn;
    for (int l = tid; l < Ln; l += 256)
        attn[b * Ln + l] = expf(g_score[b * Ln + l] - s_max) * s_inv;
}

// ---------------------------------------------------------------------------
// Kernel 5: context[b,d] = sum_l attn[b,l] * values[b,l,d]
// ---------------------------------------------------------------------------
__global__ __launch_bounds__(1024) void context_kernel(
    const float* __restrict__ values, float* __restrict__ out)
{
    int lc = blockIdx.x;   // 8 chunks of 256
    int b  = blockIdx.y;   // 32
    int d  = threadIdx.x;  // 1024
    const float* attn = out + Bn * Dn + b * Ln + lc * 256;
    const float* v = values + (size_t)b * Ln * Dn + (size_t)lc * 256 * Dn;
    float acc = 0.f;
#pragma unroll 4
    for (int l = 0; l < 256; l++)
        acc += __ldg(&attn[l]) * v[(size_t)l * Dn + d];
    atomicAdd(&out[b * Dn + d], acc);
}

// ---------------------------------------------------------------------------
extern "C" void kernel_launch(void* const* d_in, const int* in_sizes, int n_in,
                              void* d_out, int out_size)
{
    const float* query = (const float*)d_in[0];
    const float* values = (const float*)d_in[1];
    const float* mask = (const float*)d_in[2];
    const float* prev = (const float*)d_in[3];
    const int*   tstep = (const int*)d_in[4];
    const float* Wh = (const float*)d_in[5];
    const float* bh = (const float*)d_in[6];
    const float* Wv = (const float*)d_in[7];
    const float* bv = (const float*)d_in[8];
    const float* Wp = (const float*)d_in[9];
    const float* bp = (const float*)d_in[10];
    const float* Wm = (const float*)d_in[11];
    const float* bm = (const float*)d_in[12];
    const float* vw = (const float*)d_in[13];
    const float* vb = (const float*)d_in[14];
    float* out = (float*)d_out;

    prep_kernel<<<Bn, 512>>>(query, mask, tstep, Wh, bh, bv, Wp, bp, bm);
    init_kernel<<<(Bn * Ln + 255) / 256, 256>>>(mask, vb, out);
    dim3 gs(Un / TN, Ln / TM, Bn);
    score_kernel<<<gs, 256>>>(values, Wv, Wp, Wm, vw, prev);
    softmax_kernel<<<Bn, 256>>>(out);
    context_kernel<<<dim3(8, Bn), 1024>>>(values, out);
}

// round 2
// speedup vs baseline: 2.6403x; 2.6403x over previous
#include <cuda_runtime.h>
#include <math.h>

#define Bn 32
#define Ln 2048
#define Dn 1024
#define Un 512

#define TM 128
#define TN 128
#define KC 32
#define NST 3
#define NSTAGES (Dn / KC)   // 32

// static device scratch (no runtime allocation)
__device__ __align__(16) float g_vals[(size_t)Bn * Ln * Dn];  // tf32-rounded values
__device__ __align__(16) float g_wvT[Un * Dn];                // tf32-rounded Wv^T [u][k]
__device__ float g_ubias[Bn * Un];
__device__ float g_score[Bn * Ln];

__device__ __forceinline__ float tf32r(float f) {
    unsigned u;
    asm("cvt.rna.tf32.f32 %0, %1;" : "=r"(u) : "f"(f));
    return __uint_as_float(u);
}
__device__ __forceinline__ float tanh_fast(float x) {
    float y;
    asm("tanh.approx.f32 %0, %1;" : "=f"(y) : "f"(x));
    return y;
}

// ---------------------------------------------------------------------------
// Convert passes: values -> tf32 (rna), Wv -> transposed tf32 [u][k]
// ---------------------------------------------------------------------------
__global__ void convert_values_kernel(const float4* __restrict__ src) {
    size_t i = (size_t)blockIdx.x * blockDim.x + threadIdx.x;
    float4 a = src[i];
    float4 o = make_float4(tf32r(a.x), tf32r(a.y), tf32r(a.z), tf32r(a.w));
    reinterpret_cast<float4*>(g_vals)[i] = o;
}
__global__ void convert_wv_kernel(const float* __restrict__ Wv) {
    int i = blockIdx.x * blockDim.x + threadIdx.x;  // i = u*1024 + k
    int u = i >> 10, k = i & 1023;
    g_wvT[i] = tf32r(Wv[k * Un + u]);
}

// ---------------------------------------------------------------------------
// Kernel: per-batch prep (q@Wh + fused l-independent bias terms)
// ---------------------------------------------------------------------------
__global__ void prep_kernel(const float* __restrict__ query,
                            const float* __restrict__ mask,
                            const int*   __restrict__ tstep,
                            const float* __restrict__ Wh,
                            const float* __restrict__ bh,
                            const float* __restrict__ bv,
                            const float* __restrict__ Wp,
                            const float* __restrict__ bp,
                            const float* __restrict__ bm)
{
    int b = blockIdx.x;
    int tid = threadIdx.x;                 // 512 threads
    __shared__ float qs[Dn];
    __shared__ float red[512];
    __shared__ float s_loglen, s_logts;

    float cnt = 0.f;
    for (int l = tid; l < Ln; l += 512)
        cnt += (mask[b * Ln + l] == 0.0f) ? 1.0f : 0.0f;
    red[tid] = cnt;
    __syncthreads();
    for (int s = 256; s > 0; s >>= 1) {
        if (tid < s) red[tid] += red[tid + s];
        __syncthreads();
    }
    if (tid == 0) {
        s_loglen = logf(1.0f + red[0]);
        int iv = tstep[0];
        float ts;
        if (iv >= 0 && iv < 1000000) ts = (float)iv;
        else ts = __int_as_float(iv);
        s_logts = logf(1.0f + ts);
    }
    for (int d = tid; d < Dn; d += 512) qs[d] = query[b * Dn + d];
    __syncthreads();

    int u = tid;
    float acc = 0.f;
#pragma unroll 8
    for (int d = 0; d < Dn; d++) acc += qs[d] * Wh[d * Un + u];
    g_ubias[b * Un + u] = acc + bh[u] + bv[u] + bp[u] + bm[u]
                        + s_logts * Wp[u] + s_loglen * Wp[2 * Un + u];
}

// ---------------------------------------------------------------------------
// Kernel: score init (vb + mask penalty), zero context output region
// ---------------------------------------------------------------------------
__global__ void init_kernel(const float* __restrict__ mask,
                            const float* __restrict__ vb,
                            float* __restrict__ out)
{
    int i = blockIdx.x * blockDim.x + threadIdx.x;
    if (i < Bn * Ln) g_score[i] = vb[0] + mask[i] * -1e9f;
    if (i < Bn * Dn) out[i] = 0.0f;
}

// ---------------------------------------------------------------------------
// Kernel: fused score GEMM (tf32 mma, cp.async 3-stage pipeline, swizzled)
//   block: 256 thr = 8 warps (2M x 4N); warp tile 64x32; TM=128, TN=128
// ---------------------------------------------------------------------------
__global__ __launch_bounds__(256, 2) void score_kernel(
    const float* __restrict__ Wp,
    const float* __restrict__ Wm,
    const float* __restrict__ vw,
    const float* __restrict__ prev)
{
    extern __shared__ float sm[];
    float* As    = sm;                        // NST*TM*KC
    float* Bs    = sm + NST * TM * KC;        // NST*TN*KC
    float* eb    = Bs + NST * TN * KC;        // 8*TN
    float* prevs = eb + 8 * TN;               // TM+4

    int utile = blockIdx.x, ltile = blockIdx.y, bb = blockIdx.z;
    int l0 = ltile * TM, u0 = utile * TN;
    int tid = threadIdx.x, lane = tid & 31, warp = tid >> 5;
    int warpM = warp >> 2, warpN = warp & 3;
    int qa = lane & 3, rr = lane >> 2;

    const float* abase = g_vals + (size_t)bb * Ln * Dn + (size_t)l0 * Dn;
    const float* bbase = g_wvT + (size_t)u0 * Dn;

    // epilogue staging (visible by first in-loop barrier)
    if (tid < TN) {
        eb[tid]          = g_ubias[bb * Un + u0 + tid];
        eb[TN + tid]     = Wp[Un + u0 + tid];
        eb[2 * TN + tid] = vw[u0 + tid];
#pragma unroll
        for (int j = 0; j < 5; j++) eb[(3 + j) * TN + tid] = Wm[j * Un + u0 + tid];
    }
    if (tid < TM + 4) {
        int gl = l0 - 2 + tid;
        prevs[tid] = (gl >= 0 && gl < Ln) ? prev[bb * Ln + gl] : 0.0f;
    }

    float acc[4][4][4];
#pragma unroll
    for (int a = 0; a < 4; a++)
#pragma unroll
        for (int n = 0; n < 4; n++)
#pragma unroll
            for (int c = 0; c < 4; c++) acc[a][n][c] = 0.f;

    auto issue_stage = [&](int s) {
        int so = (s % NST) * (TM * KC);
        const float* ab = abase + s * KC;
        const float* bsrc = bbase + s * KC;
#pragma unroll
        for (int i = 0; i < 4; i++) {
            int p = tid + 256 * i;
            int r = p >> 3, g = p & 7;
            unsigned da = (unsigned)__cvta_generic_to_shared(
                &As[so + r * KC + 4 * (g ^ (r & 7))]);
            const float* sa = ab + (size_t)r * Dn + 4 * g;
            asm volatile("cp.async.cg.shared.global [%0], [%1], 16;" ::"r"(da), "l"(sa));
            unsigned db = (unsigned)__cvta_generic_to_shared(
                &Bs[so + r * KC + 4 * (g ^ (r & 7))]);
            const float* sb = bsrc + (size_t)r * Dn + 4 * g;
            asm volatile("cp.async.cg.shared.global [%0], [%1], 16;" ::"r"(db), "l"(sb));
        }
    };

    issue_stage(0);
    asm volatile("cp.async.commit_group;");
    issue_stage(1);
    asm volatile("cp.async.commit_group;");

    for (int s = 0; s < NSTAGES; s++) {
        asm volatile("cp.async.wait_group 1;");
        __syncthreads();
        if (s + 2 < NSTAGES) issue_stage(s + 2);
        asm volatile("cp.async.commit_group;");

        const float* Ac = As + (s % NST) * (TM * KC);
        const float* Bc = Bs + (s % NST) * (TM * KC);
#pragma unroll
        for (int k8 = 0; k8 < 4; k8++) {
            int g0 = 2 * k8;
            unsigned af[4][4];
#pragma unroll
            for (int mt = 0; mt < 4; mt++) {
                int r1 = warpM * 64 + mt * 16 + rr;
                int r2 = r1 + 8;
                af[mt][0] = __float_as_uint(Ac[r1 * KC + qa + 4 * (g0 ^ (r1 & 7))]);
                af[mt][1] = __float_as_uint(Ac[r2 * KC + qa + 4 * (g0 ^ (r2 & 7))]);
                af[mt][2] = __float_as_uint(Ac[r1 * KC + qa + 4 * ((g0 + 1) ^ (r1 & 7))]);
                af[mt][3] = __float_as_uint(Ac[r2 * KC + qa + 4 * ((g0 + 1) ^ (r2 & 7))]);
            }
#pragma unroll
            for (int nt = 0; nt < 4; nt++) {
                int n = warpN * 32 + nt * 8 + rr;
                unsigned b0 = __float_as_uint(Bc[n * KC + qa + 4 * (g0 ^ (n & 7))]);
                unsigned b1 = __float_as_uint(Bc[n * KC + qa + 4 * ((g0 + 1) ^ (n & 7))]);
#pragma unroll
                for (int mt = 0; mt < 4; mt++) {
                    asm volatile(
                        "mma.sync.aligned.m16n8k8.row.col.f32.tf32.tf32.f32 "
                        "{%0,%1,%2,%3}, {%4,%5,%6,%7}, {%8,%9}, {%0,%1,%2,%3};"
                        : "+f"(acc[mt][nt][0]), "+f"(acc[mt][nt][1]),
                          "+f"(acc[mt][nt][2]), "+f"(acc[mt][nt][3])
                        : "r"(af[mt][0]), "r"(af[mt][1]), "r"(af[mt][2]), "r"(af[mt][3]),
                          "r"(b0), "r"(b1));
                }
            }
        }
    }

    // ---- epilogue ----
#pragma unroll
    for (int mt = 0; mt < 4; mt++) {
#pragma unroll
        for (int half = 0; half < 2; half++) {
            int rl = warpM * 64 + mt * 16 + rr + 8 * half;
            float ll = logf(2.0f + (float)(l0 + rl));
            float sumv = 0.f;
#pragma unroll
            for (int nt = 0; nt < 4; nt++) {
#pragma unroll
                for (int j = 0; j < 2; j++) {
                    int col = warpN * 32 + nt * 8 + qa * 2 + j;
                    float sc = acc[mt][nt][half * 2 + j] + eb[col] + ll * eb[TN + col];
#pragma unroll
                    for (int w = 0; w < 5; w++)
                        sc += prevs[rl + w] * eb[(3 + w) * TN + col];
                    sumv += tanh_fast(sc) * eb[2 * TN + col];
                }
            }
            sumv += __shfl_xor_sync(0xffffffffu, sumv, 1);
            sumv += __shfl_xor_sync(0xffffffffu, sumv, 2);
            if (qa == 0) atomicAdd(&g_score[bb * Ln + l0 + rl], sumv);
        }
    }
}

// ---------------------------------------------------------------------------
// Kernel: softmax over L per batch -> attention weights into d_out
// ---------------------------------------------------------------------------
__global__ void softmax_kernel(float* __restrict__ out)
{
    int b = blockIdx.x;
    int tid = threadIdx.x;   // 256
    __shared__ float red[256];
    __shared__ float s_max, s_inv;

    float m = -1e30f;
    for (int l = tid; l < Ln; l += 256) m = fmaxf(m, g_score[b * Ln + l]);
    red[tid] = m;
    __syncthreads();
    for (int s = 128; s > 0; s >>= 1) {
        if (tid < s) red[tid] = fmaxf(red[tid], red[tid + s]);
        __syncthreads();
    }
    if (tid == 0) s_max = red[0];
    __syncthreads();

    float sum = 0.f;
    for (int l = tid; l < Ln; l += 256) sum += expf(g_score[b * Ln + l] - s_max);
    red[tid] = sum;
    __syncthreads();
    for (int s = 128; s > 0; s >>= 1) {
        if (tid < s) red[tid] += red[tid + s];
        __syncthreads();
    }
    if (tid == 0) s_inv = 1.0f / red[0];
    __syncthreads();

    float* attn = out + Bn * Dn;
    for (int l = tid; l < Ln; l += 256)
        attn[b * Ln + l] = expf(g_score[b * Ln + l] - s_max) * s_inv;
}

// ---------------------------------------------------------------------------
// Kernel: context[b,d] = sum_l attn[b,l] * values[b,l,d]
// ---------------------------------------------------------------------------
__global__ __launch_bounds__(1024) void context_kernel(
    const float* __restrict__ values, float* __restrict__ out)
{
    int lc = blockIdx.x;   // 8 chunks of 256
    int b  = blockIdx.y;   // 32
    int d  = threadIdx.x;  // 1024
    const float* attn = out + Bn * Dn + b * Ln + lc * 256;
    const float* v = values + (size_t)b * Ln * Dn + (size_t)lc * 256 * Dn;
    float acc = 0.f;
#pragma unroll 4
    for (int l = 0; l < 256; l++)
        acc += __ldg(&attn[l]) * v[(size_t)l * Dn + d];
    atomicAdd(&out[b * Dn + d], acc);
}

// ---------------------------------------------------------------------------
extern "C" void kernel_launch(void* const* d_in, const int* in_sizes, int n_in,
                              void* d_out, int out_size)
{
    const float* query = (const float*)d_in[0];
    const float* values = (const float*)d_in[1];
    const float* mask = (const float*)d_in[2];
    const float* prev = (const float*)d_in[3];
    const int*   tstep = (const int*)d_in[4];
    const float* Wh = (const float*)d_in[5];
    const float* bh = (const float*)d_in[6];
    const float* Wv = (const float*)d_in[7];
    const float* bv = (const float*)d_in[8];
    const float* Wp = (const float*)d_in[9];
    const float* bp = (const float*)d_in[10];
    const float* Wm = (const float*)d_in[11];
    const float* bm = (const float*)d_in[12];
    const float* vw = (const float*)d_in[13];
    const float* vb = (const float*)d_in[14];
    float* out = (float*)d_out;

    const int smem_bytes = (NST * TM * KC + NST * TN * KC + 8 * TN + TM + 8) * 4;
    cudaFuncSetAttribute(score_kernel,
                         cudaFuncAttributeMaxDynamicSharedMemorySize, smem_bytes);

    convert_values_kernel<<<(Bn * Ln * Dn / 4) / 256, 256>>>((const float4*)values);
    convert_wv_kernel<<<(Un * Dn) / 256, 256>>>(Wv);
    prep_kernel<<<Bn, 512>>>(query, mask, tstep, Wh, bh, bv, Wp, bp, bm);
    init_kernel<<<(Bn * Ln + 255) / 256, 256>>>(mask, vb, out);
    dim3 gs(Un / TN, Ln / TM, Bn);
    score_kernel<<<gs, 256, smem_bytes>>>(Wp, Wm, vw, prev);
    softmax_kernel<<<Bn, 256>>>(out);
    context_kernel<<<dim3(8, Bn), 1024>>>(values, out);
}

// round 3
// speedup vs baseline: 3.6420x; 1.3794x over previous
#include <cuda_runtime.h>
#include <cuda_fp16.h>
#include <math.h>

#define Bn 32
#define Ln 2048
#define Dn 1024
#define Un 512

#define TM 128
#define TN 128
#define KC 32            // halfs per k-chunk (64 B rows)
#define NST 4
#define NSTAGES (Dn / KC)   // 32

// static device scratch (no runtime allocation)
__device__ __align__(16) __half g_valsh[(size_t)Bn * Ln * Dn];  // fp16 values
__device__ __align__(16) __half g_wvTh[Un * Dn];                // fp16 Wv^T [u][k]
__device__ float g_ubias[Bn * Un];
__device__ float g_score[Bn * Ln];

__device__ __forceinline__ float tanh_fast(float x) {
    float y;
    asm("tanh.approx.f32 %0, %1;" : "=f"(y) : "f"(x));
    return y;
}
__device__ __forceinline__ int swz(int r) { return (r ^ (r >> 2)) & 3; }

// ---------------------------------------------------------------------------
// Convert: values -> fp16 (rn). 8 elems / thread.
// ---------------------------------------------------------------------------
__global__ void convert_values_kernel(const float4* __restrict__ src) {
    size_t i = (size_t)blockIdx.x * blockDim.x + threadIdx.x;
    float4 a = src[2 * i], b = src[2 * i + 1];
    union { uint4 u; __half2 h[4]; } o;
    o.h[0] = __floats2half2_rn(a.x, a.y);
    o.h[1] = __floats2half2_rn(a.z, a.w);
    o.h[2] = __floats2half2_rn(b.x, b.y);
    o.h[3] = __floats2half2_rn(b.z, b.w);
    reinterpret_cast<uint4*>(g_valsh)[i] = o.u;
}
__global__ void convert_wv_kernel(const float* __restrict__ Wv) {
    int i = blockIdx.x * blockDim.x + threadIdx.x;  // i = u*1024 + k
    int u = i >> 10, k = i & 1023;
    g_wvTh[i] = __float2half_rn(Wv[k * Un + u]);
}

// ---------------------------------------------------------------------------
// Per-batch prep (q@Wh + fused l-independent bias terms)
// ---------------------------------------------------------------------------
__global__ void prep_kernel(const float* __restrict__ query,
                            const float* __restrict__ mask,
                            const int*   __restrict__ tstep,
                            const float* __restrict__ Wh,
                            const float* __restrict__ bh,
                            const float* __restrict__ bv,
                            const float* __restrict__ Wp,
                            const float* __restrict__ bp,
                            const float* __restrict__ bm)
{
    int b = blockIdx.x;
    int tid = threadIdx.x;                 // 512 threads
    __shared__ float qs[Dn];
    __shared__ float red[512];
    __shared__ float s_loglen, s_logts;

    float cnt = 0.f;
    for (int l = tid; l < Ln; l += 512)
        cnt += (mask[b * Ln + l] == 0.0f) ? 1.0f : 0.0f;
    red[tid] = cnt;
    __syncthreads();
    for (int s = 256; s > 0; s >>= 1) {
        if (tid < s) red[tid] += red[tid + s];
        __syncthreads();
    }
    if (tid == 0) {
        s_loglen = logf(1.0f + red[0]);
        int iv = tstep[0];
        float ts;
        if (iv >= 0 && iv < 1000000) ts = (float)iv;
        else ts = __int_as_float(iv);
        s_logts = logf(1.0f + ts);
    }
    for (int d = tid; d < Dn; d += 512) qs[d] = query[b * Dn + d];
    __syncthreads();

    int u = tid;
    float acc = 0.f;
#pragma unroll 8
    for (int d = 0; d < Dn; d++) acc += qs[d] * Wh[d * Un + u];
    g_ubias[b * Un + u] = acc + bh[u] + bv[u] + bp[u] + bm[u]
                        + s_logts * Wp[u] + s_loglen * Wp[2 * Un + u];
}

// ---------------------------------------------------------------------------
// Score init (vb + mask penalty), zero context output region
// ---------------------------------------------------------------------------
__global__ void init_kernel(const float* __restrict__ mask,
                            const float* __restrict__ vb,
                            float* __restrict__ out)
{
    int i = blockIdx.x * blockDim.x + threadIdx.x;
    if (i < Bn * Ln) g_score[i] = vb[0] + mask[i] * -1e9f;
    if (i < Bn * Dn) out[i] = 0.0f;
}

// ---------------------------------------------------------------------------
// Fused score GEMM (fp16 m16n8k16, 4-stage cp.async, XOR swizzle) + epilogue
//   256 thr = 8 warps (2M x 4N); warp tile 64x32; TM=128, TN=128
// ---------------------------------------------------------------------------
__global__ __launch_bounds__(256, 2) void score_kernel(
    const float* __restrict__ Wp,
    const float* __restrict__ Wm,
    const float* __restrict__ vw,
    const float* __restrict__ prev)
{
    extern __shared__ char smraw[];
    __half* As = (__half*)smraw;                       // NST*TM*KC halfs
    __half* Bs = As + NST * TM * KC;                   // NST*TN*KC halfs
    float*  eb = (float*)(Bs + NST * TN * KC);         // 8*TN floats
    float*  prevs = eb + 8 * TN;                       // TM+4

    int utile = blockIdx.x, ltile = blockIdx.y, bb = blockIdx.z;
    int l0 = ltile * TM, u0 = utile * TN;
    int tid = threadIdx.x, lane = tid & 31, warp = tid >> 5;
    int warpM = warp >> 2, warpN = warp & 3;
    int qa = lane & 3, rr = lane >> 2;

    const __half* abase = g_valsh + (size_t)bb * Ln * Dn + (size_t)l0 * Dn;
    const __half* bbase = g_wvTh + (size_t)u0 * Dn;

    // epilogue staging (visible via in-loop barriers)
    if (tid < TN) {
        eb[tid]          = g_ubias[bb * Un + u0 + tid];
        eb[TN + tid]     = Wp[Un + u0 + tid];
        eb[2 * TN + tid] = vw[u0 + tid];
#pragma unroll
        for (int j = 0; j < 5; j++) eb[(3 + j) * TN + tid] = Wm[j * Un + u0 + tid];
    }
    if (tid < TM + 4) {
        int gl = l0 - 2 + tid;
        prevs[tid] = (gl >= 0 && gl < Ln) ? prev[bb * Ln + gl] : 0.0f;
    }

    // precompute loop-invariant fragment smem offsets (halfs), kk=0
    int aoff[4][4], boff[4][2];
#pragma unroll
    for (int mt = 0; mt < 4; mt++) {
        int r1 = warpM * 64 + mt * 16 + rr, r2 = r1 + 8;
        int s1 = swz(r1), s2 = swz(r2);
        aoff[mt][0] = r1 * KC + 8 * (0 ^ s1) + 2 * qa;
        aoff[mt][1] = r2 * KC + 8 * (0 ^ s2) + 2 * qa;
        aoff[mt][2] = r1 * KC + 8 * (1 ^ s1) + 2 * qa;
        aoff[mt][3] = r2 * KC + 8 * (1 ^ s2) + 2 * qa;
    }
#pragma unroll
    for (int nt = 0; nt < 4; nt++) {
        int n = warpN * 32 + nt * 8 + rr;
        int sn = swz(n);
        boff[nt][0] = n * KC + 8 * (0 ^ sn) + 2 * qa;
        boff[nt][1] = n * KC + 8 * (1 ^ sn) + 2 * qa;
    }

    float acc[4][4][4];
#pragma unroll
    for (int a = 0; a < 4; a++)
#pragma unroll
        for (int n = 0; n < 4; n++)
#pragma unroll
            for (int c = 0; c < 4; c++) acc[a][n][c] = 0.f;

    auto issue_stage = [&](int s) {
        int so = (s % NST) * (TM * KC);
        const __half* ab = abase + s * KC;
        const __half* bsrc = bbase + s * KC;
#pragma unroll
        for (int i = 0; i < 2; i++) {
            int p = tid + 256 * i;
            int r = p >> 2, c = p & 3;
            unsigned da = (unsigned)__cvta_generic_to_shared(
                &As[so + r * KC + 8 * (c ^ swz(r))]);
            asm volatile("cp.async.cg.shared.global [%0], [%1], 16;"
                         ::"r"(da), "l"(ab + (size_t)r * Dn + 8 * c));
            unsigned db = (unsigned)__cvta_generic_to_shared(
                &Bs[so + r * KC + 8 * (c ^ swz(r))]);
            asm volatile("cp.async.cg.shared.global [%0], [%1], 16;"
                         ::"r"(db), "l"(bsrc + (size_t)r * Dn + 8 * c));
        }
    };

    issue_stage(0);
    asm volatile("cp.async.commit_group;");
    issue_stage(1);
    asm volatile("cp.async.commit_group;");
    issue_stage(2);
    asm volatile("cp.async.commit_group;");

    for (int s = 0; s < NSTAGES; s++) {
        asm volatile("cp.async.wait_group 2;");
        __syncthreads();
        if (s + 3 < NSTAGES) issue_stage(s + 3);
        asm volatile("cp.async.commit_group;");

        const __half* Ac = As + (s % NST) * (TM * KC);
        const __half* Bc = Bs + (s % NST) * (TN * KC);
#pragma unroll
        for (int kk = 0; kk < 2; kk++) {
            int x = kk ? 16 : 0;   // kk=1 flips chunk bit1 -> offset ^ 16 halfs
            unsigned af[4][4];
#pragma unroll
            for (int mt = 0; mt < 4; mt++) {
#pragma unroll
                for (int j = 0; j < 4; j++)
                    af[mt][j] = *(const unsigned*)&Ac[aoff[mt][j] ^ x];
            }
#pragma unroll
            for (int nt = 0; nt < 4; nt++) {
                unsigned b0 = *(const unsigned*)&Bc[boff[nt][0] ^ x];
                unsigned b1 = *(const unsigned*)&Bc[boff[nt][1] ^ x];
#pragma unroll
                for (int mt = 0; mt < 4; mt++) {
                    asm volatile(
                        "mma.sync.aligned.m16n8k16.row.col.f32.f16.f16.f32 "
                        "{%0,%1,%2,%3}, {%4,%5,%6,%7}, {%8,%9}, {%0,%1,%2,%3};"
                        : "+f"(acc[mt][nt][0]), "+f"(acc[mt][nt][1]),
                          "+f"(acc[mt][nt][2]), "+f"(acc[mt][nt][3])
                        : "r"(af[mt][0]), "r"(af[mt][1]), "r"(af[mt][2]), "r"(af[mt][3]),
                          "r"(b0), "r"(b1));
                }
            }
        }
    }

    // ---- epilogue ----
#pragma unroll
    for (int mt = 0; mt < 4; mt++) {
#pragma unroll
        for (int half = 0; half < 2; half++) {
            int rl = warpM * 64 + mt * 16 + rr + 8 * half;
            float ll = logf(2.0f + (float)(l0 + rl));
            float sumv = 0.f;
#pragma unroll
            for (int nt = 0; nt < 4; nt++) {
#pragma unroll
                for (int j = 0; j < 2; j++) {
                    int col = warpN * 32 + nt * 8 + qa * 2 + j;
                    float sc = acc[mt][nt][half * 2 + j] + eb[col] + ll * eb[TN + col];
#pragma unroll
                    for (int w = 0; w < 5; w++)
                        sc += prevs[rl + w] * eb[(3 + w) * TN + col];
                    sumv += tanh_fast(sc) * eb[2 * TN + col];
                }
            }
            sumv += __shfl_xor_sync(0xffffffffu, sumv, 1);
            sumv += __shfl_xor_sync(0xffffffffu, sumv, 2);
            if (qa == 0) atomicAdd(&g_score[bb * Ln + l0 + rl], sumv);
        }
    }
}

// ---------------------------------------------------------------------------
// Softmax over L per batch -> attention weights into d_out
// ---------------------------------------------------------------------------
__global__ void softmax_kernel(float* __restrict__ out)
{
    int b = blockIdx.x;
    int tid = threadIdx.x;   // 256
    __shared__ float red[256];
    __shared__ float s_max, s_inv;

    float m = -1e30f;
    for (int l = tid; l < Ln; l += 256) m = fmaxf(m, g_score[b * Ln + l]);
    red[tid] = m;
    __syncthreads();
    for (int s = 128; s > 0; s >>= 1) {
        if (tid < s) red[tid] = fmaxf(red[tid], red[tid + s]);
        __syncthreads();
    }
    if (tid == 0) s_max = red[0];
    __syncthreads();

    float sum = 0.f;
    for (int l = tid; l < Ln; l += 256) sum += expf(g_score[b * Ln + l] - s_max);
    red[tid] = sum;
    __syncthreads();
    for (int s = 128; s > 0; s >>= 1) {
        if (tid < s) red[tid] += red[tid + s];
        __syncthreads();
    }
    if (tid == 0) s_inv = 1.0f / red[0];
    __syncthreads();

    float* attn = out + Bn * Dn;
    for (int l = tid; l < Ln; l += 256)
        attn[b * Ln + l] = expf(g_score[b * Ln + l] - s_max) * s_inv;
}

// ---------------------------------------------------------------------------
// context[b,d] = sum_l attn[b,l] * values_h[b,l,d]   (half2 path)
// ---------------------------------------------------------------------------
__global__ __launch_bounds__(512) void context_kernel(float* __restrict__ out)
{
    int lc = blockIdx.x;    // 8 chunks of 256 rows
    int b  = blockIdx.y;    // 32
    int d2 = threadIdx.x;   // 512 (half2 columns)
    const float* attn = out + Bn * Dn + b * Ln + lc * 256;
    const __half2* v = reinterpret_cast<const __half2*>(g_valsh)
                     + ((size_t)b * Ln + (size_t)lc * 256) * (Dn / 2) + d2;
    float ax = 0.f, ay = 0.f;
#pragma unroll 4
    for (int l = 0; l < 256; l++) {
        float2 f = __half22float2(v[(size_t)l * (Dn / 2)]);
        float w = __ldg(&attn[l]);
        ax += w * f.x;
        ay += w * f.y;
    }
    atomicAdd(&out[b * Dn + 2 * d2], ax);
    atomicAdd(&out[b * Dn + 2 * d2 + 1], ay);
}

// ---------------------------------------------------------------------------
extern "C" void kernel_launch(void* const* d_in, const int* in_sizes, int n_in,
                              void* d_out, int out_size)
{
    const float* query = (const float*)d_in[0];
    const float* values = (const float*)d_in[1];
    const float* mask = (const float*)d_in[2];
    const float* prev = (const float*)d_in[3];
    const int*   tstep = (const int*)d_in[4];
    const float* Wh = (const float*)d_in[5];
    const float* bh = (const float*)d_in[6];
    const float* Wv = (const float*)d_in[7];
    const float* bv = (const float*)d_in[8];
    const float* Wp = (const float*)d_in[9];
    const float* bp = (const float*)d_in[10];
    const float* Wm = (const float*)d_in[11];
    const float* bm = (const float*)d_in[12];
    const float* vw = (const float*)d_in[13];
    const float* vb = (const float*)d_in[14];
    float* out = (float*)d_out;

    const int smem_bytes = (NST * TM * KC + NST * TN * KC) * 2
                         + (8 * TN + TM + 8) * 4;
    cudaFuncSetAttribute(score_kernel,
                         cudaFuncAttributeMaxDynamicSharedMemorySize, smem_bytes);

    convert_values_kernel<<<((size_t)Bn * Ln * Dn / 8) / 256, 256>>>((const float4*)values);
    convert_wv_kernel<<<(Un * Dn) / 256, 256>>>(Wv);
    prep_kernel<<<Bn, 512>>>(query, mask, tstep, Wh, bh, bv, Wp, bp, bm);
    init_kernel<<<(Bn * Ln + 255) / 256, 256>>>(mask, vb, out);
    dim3 gs(Un / TN, Ln / TM, Bn);
    score_kernel<<<gs, 256, smem_bytes>>>(Wp, Wm, vw, prev);
    softmax_kernel<<<Bn, 256>>>(out);
    context_kernel<<<dim3(8, Bn), 512>>>(out);
}

// round 5
// speedup vs baseline: 3.9737x; 1.0911x over previous
#include <cuda_runtime.h>
#include <cuda_fp16.h>
#include <math.h>

#define Bn 32
#define Ln 2048
#define Dn 1024
#define Un 512

#define TM 128
#define TN 128
#define KC 32            // halfs per k-chunk (64 B rows)
#define NST 4
#define NSTAGES (Dn / KC)   // 32

// static device scratch (no runtime allocation)
__device__ __align__(16) __half g_valsh[(size_t)Bn * Ln * Dn];  // fp16 values
__device__ __align__(16) __half g_wvTh[Un * Dn];                // fp16 Wv^T [u][k]
__device__ float g_ubias[Bn * Un];
__device__ float g_score[Bn * Ln];

__device__ __forceinline__ float tanh_fast(float x) {
    float y;
    asm("tanh.approx.f32 %0, %1;" : "=f"(y) : "f"(x));
    return y;
}
__device__ __forceinline__ int swz(int r) { return (r ^ (r >> 2)) & 3; }

__device__ __forceinline__ void ldsm4(unsigned addr, unsigned& r0, unsigned& r1,
                                      unsigned& r2, unsigned& r3) {
    asm volatile("ldmatrix.sync.aligned.m8n8.x4.shared.b16 {%0,%1,%2,%3}, [%4];"
                 : "=r"(r0), "=r"(r1), "=r"(r2), "=r"(r3) : "r"(addr));
}

// ---------------------------------------------------------------------------
// Convert: values -> fp16 (rn), 8 elems/thread; Wv -> transposed fp16 [u][k]
// ---------------------------------------------------------------------------
__global__ void convert_values_kernel(const float4* __restrict__ src) {
    size_t i = (size_t)blockIdx.x * blockDim.x + threadIdx.x;
    float4 a = src[2 * i], b = src[2 * i + 1];
    union { uint4 u; __half2 h[4]; } o;
    o.h[0] = __floats2half2_rn(a.x, a.y);
    o.h[1] = __floats2half2_rn(a.z, a.w);
    o.h[2] = __floats2half2_rn(b.x, b.y);
    o.h[3] = __floats2half2_rn(b.z, b.w);
    reinterpret_cast<uint4*>(g_valsh)[i] = o.u;
}
__global__ void convert_wv_kernel(const float* __restrict__ Wv) {
    int i = blockIdx.x * blockDim.x + threadIdx.x;  // i = u*1024 + k
    int u = i >> 10, k = i & 1023;
    g_wvTh[i] = __float2half_rn(Wv[k * Un + u]);
}

// ---------------------------------------------------------------------------
// Per-batch prep (q@Wh + fused l-independent bias terms)
// ---------------------------------------------------------------------------
__global__ void prep_kernel(const float* __restrict__ query,
                            const float* __restrict__ mask,
                            const int*   __restrict__ tstep,
                            const float* __restrict__ Wh,
                            const float* __restrict__ bh,
                            const float* __restrict__ bv,
                            const float* __restrict__ Wp,
                            const float* __restrict__ bp,
                            const float* __restrict__ bm)
{
    int b = blockIdx.x;
    int tid = threadIdx.x;                 // 512 threads
    __shared__ float qs[Dn];
    __shared__ float red[512];
    __shared__ float s_loglen, s_logts;

    float cnt = 0.f;
    for (int l = tid; l < Ln; l += 512)
        cnt += (mask[b * Ln + l] == 0.0f) ? 1.0f : 0.0f;
    red[tid] = cnt;
    __syncthreads();
    for (int s = 256; s > 0; s >>= 1) {
        if (tid < s) red[tid] += red[tid + s];
        __syncthreads();
    }
    if (tid == 0) {
        s_loglen = logf(1.0f + red[0]);
        int iv = tstep[0];
        float ts;
        if (iv >= 0 && iv < 1000000) ts = (float)iv;
        else ts = __int_as_float(iv);
        s_logts = logf(1.0f + ts);
    }
    for (int d = tid; d < Dn; d += 512) qs[d] = query[b * Dn + d];
    __syncthreads();

    int u = tid;
    float acc = 0.f;
#pragma unroll 8
    for (int d = 0; d < Dn; d++) acc += qs[d] * Wh[d * Un + u];
    g_ubias[b * Un + u] = acc + bh[u] + bv[u] + bp[u] + bm[u]
                        + s_logts * Wp[u] + s_loglen * Wp[2 * Un + u];
}

// ---------------------------------------------------------------------------
// Score init (vb + mask penalty), zero context output region
// ---------------------------------------------------------------------------
__global__ void init_kernel(const float* __restrict__ mask,
                            const float* __restrict__ vb,
                            float* __restrict__ out)
{
    int i = blockIdx.x * blockDim.x + threadIdx.x;
    if (i < Bn * Ln) g_score[i] = vb[0] + mask[i] * -1e9f;
    if (i < Bn * Dn) out[i] = 0.0f;
}

// ---------------------------------------------------------------------------
// Fused score GEMM (fp16 m16n8k16, ldmatrix fragments, 4-stage cp.async)
//   256 thr = 8 warps (2M x 4N); warp tile 64x32; TM=128, TN=128
// ---------------------------------------------------------------------------
__global__ __launch_bounds__(256, 2) void score_kernel(
    const float* __restrict__ Wp,
    const float* __restrict__ Wm,
    const float* __restrict__ vw,
    const float* __restrict__ prev)
{
    extern __shared__ char smraw[];
    __half* As = (__half*)smraw;                       // NST*TM*KC halfs (32KB)
    __half* Bs = As + NST * TM * KC;                   // NST*TN*KC halfs (32KB)
    float*  eb = (float*)(Bs + NST * TN * KC);         // 8*TN floats
    float*  prevs = eb + 8 * TN;                       // TM+4
    unsigned As_u = (unsigned)__cvta_generic_to_shared(As);
    unsigned Bs_u = (unsigned)__cvta_generic_to_shared(Bs);

    int utile = blockIdx.x, ltile = blockIdx.y, bb = blockIdx.z;
    int l0 = ltile * TM, u0 = utile * TN;
    int tid = threadIdx.x, lane = tid & 31, warp = tid >> 5;
    int warpM = warp >> 2, warpN = warp & 3;
    int qa = lane & 3, rr = lane >> 2;

    const __half* abase = g_valsh + (size_t)bb * Ln * Dn + (size_t)l0 * Dn;
    const __half* bbase = g_wvTh + (size_t)u0 * Dn;

    // epilogue staging (visible via in-loop barriers)
    if (tid < TN) {
        eb[tid]          = g_ubias[bb * Un + u0 + tid];
        eb[TN + tid]     = Wp[Un + u0 + tid];
        eb[2 * TN + tid] = vw[u0 + tid];
#pragma unroll
        for (int j = 0; j < 5; j++) eb[(3 + j) * TN + tid] = Wm[j * Un + u0 + tid];
    }
    if (tid < TM + 4) {
        int gl = l0 - 2 + tid;
        prevs[tid] = (gl >= 0 && gl < Ln) ? prev[bb * Ln + gl] : 0.0f;
    }

    // ldmatrix per-lane byte offsets within a stage buffer (kk=0; kk=1 = ^32)
    int lr = lane & 7, grp = lane >> 3;
    int rowadd = lr + 8 * (grp & 1);   // row offset within 16-row matrix pair
    int cbase = grp >> 1;              // chunk 0/1 within kk
    unsigned aoffb[4], boffb[2];
#pragma unroll
    for (int mt = 0; mt < 4; mt++) {
        int row = warpM * 64 + mt * 16 + rowadd;
        aoffb[mt] = row * 64 + 16 * (cbase ^ swz(row));
    }
#pragma unroll
    for (int ntp = 0; ntp < 2; ntp++) {
        int row = warpN * 32 + ntp * 16 + rowadd;
        boffb[ntp] = row * 64 + 16 * (cbase ^ swz(row));
    }

    float acc[4][4][4];
#pragma unroll
    for (int a = 0; a < 4; a++)
#pragma unroll
        for (int n = 0; n < 4; n++)
#pragma unroll
            for (int c = 0; c < 4; c++) acc[a][n][c] = 0.f;

    auto issue_stage = [&](int s) {
        int so = (s % NST) * (TM * KC);
        const __half* ab = abase + s * KC;
        const __half* bsrc = bbase + s * KC;
#pragma unroll
        for (int i = 0; i < 2; i++) {
            int p = tid + 256 * i;
            int r = p >> 2, c = p & 3;
            unsigned da = (unsigned)__cvta_generic_to_shared(
                &As[so + r * KC + 8 * (c ^ swz(r))]);
            asm volatile("cp.async.cg.shared.global [%0], [%1], 16;"
                         ::"r"(da), "l"(ab + (size_t)r * Dn + 8 * c));
            unsigned db = (unsigned)__cvta_generic_to_shared(
                &Bs[so + r * KC + 8 * (c ^ swz(r))]);
            asm volatile("cp.async.cg.shared.global [%0], [%1], 16;"
                         ::"r"(db), "l"(bsrc + (size_t)r * Dn + 8 * c));
        }
    };

    issue_stage(0);
    asm volatile("cp.async.commit_group;");
    issue_stage(1);
    asm volatile("cp.async.commit_group;");
    issue_stage(2);
    asm volatile("cp.async.commit_group;");

    for (int s = 0; s < NSTAGES; s++) {
        asm volatile("cp.async.wait_group 2;");
        __syncthreads();
        if (s + 3 < NSTAGES) issue_stage(s + 3);
        asm volatile("cp.async.commit_group;");

        unsigned Abuf = As_u + (unsigned)((s % NST) * (TM * KC) * 2);
        unsigned Bbuf = Bs_u + (unsigned)((s % NST) * (TN * KC) * 2);
#pragma unroll
        for (int kk = 0; kk < 2; kk++) {
            unsigned x = kk ? 32u : 0u;
            unsigned af[4][4], bf[2][4];
#pragma unroll
            for (int mt = 0; mt < 4; mt++)
                ldsm4(Abuf + (aoffb[mt] ^ x),
                      af[mt][0], af[mt][1], af[mt][2], af[mt][3]);
#pragma unroll
            for (int ntp = 0; ntp < 2; ntp++)
                ldsm4(Bbuf + (boffb[ntp] ^ x),
                      bf[ntp][0], bf[ntp][1], bf[ntp][2], bf[ntp][3]);
#pragma unroll
            for (int nt = 0; nt < 4; nt++) {
                unsigned b0 = bf[nt >> 1][nt & 1];
                unsigned b1 = bf[nt >> 1][(nt & 1) + 2];
#pragma unroll
                for (int mt = 0; mt < 4; mt++) {
                    asm volatile(
                        "mma.sync.aligned.m16n8k16.row.col.f32.f16.f16.f32 "
                        "{%0,%1,%2,%3}, {%4,%5,%6,%7}, {%8,%9}, {%0,%1,%2,%3};"
                        : "+f"(acc[mt][nt][0]), "+f"(acc[mt][nt][1]),
                          "+f"(acc[mt][nt][2]), "+f"(acc[mt][nt][3])
                        : "r"(af[mt][0]), "r"(af[mt][1]), "r"(af[mt][2]), "r"(af[mt][3]),
                          "r"(b0), "r"(b1));
                }
            }
        }
    }

    // ---- epilogue ----
#pragma unroll
    for (int mt = 0; mt < 4; mt++) {
#pragma unroll
        for (int half = 0; half < 2; half++) {
            int rl = warpM * 64 + mt * 16 + rr + 8 * half;
            float ll = logf(2.0f + (float)(l0 + rl));
            float sumv = 0.f;
#pragma unroll
            for (int nt = 0; nt < 4; nt++) {
#pragma unroll
                for (int j = 0; j < 2; j++) {
                    int col = warpN * 32 + nt * 8 + qa * 2 + j;
                    float sc = acc[mt][nt][half * 2 + j] + eb[col] + ll * eb[TN + col];
#pragma unroll
                    for (int w = 0; w < 5; w++)
                        sc += prevs[rl + w] * eb[(3 + w) * TN + col];
                    sumv += tanh_fast(sc) * eb[2 * TN + col];
                }
            }
            sumv += __shfl_xor_sync(0xffffffffu, sumv, 1);
            sumv += __shfl_xor_sync(0xffffffffu, sumv, 2);
            if (qa == 0) atomicAdd(&g_score[bb * Ln + l0 + rl], sumv);
        }
    }
}

// ---------------------------------------------------------------------------
// Softmax over L per batch -> attention weights into d_out
// ---------------------------------------------------------------------------
__global__ void softmax_kernel(float* __restrict__ out)
{
    int b = blockIdx.x;
    int tid = threadIdx.x;   // 256
    __shared__ float red[256];
    __shared__ float s_max, s_inv;

    float m = -1e30f;
    for (int l = tid; l < Ln; l += 256) m = fmaxf(m, g_score[b * Ln + l]);
    red[tid] = m;
    __syncthreads();
    for (int s = 128; s > 0; s >>= 1) {
        if (tid < s) red[tid] = fmaxf(red[tid], red[tid + s]);
        __syncthreads();
    }
    if (tid == 0) s_max = red[0];
    __syncthreads();

    float sum = 0.f;
    for (int l = tid; l < Ln; l += 256) sum += expf(g_score[b * Ln + l] - s_max);
    red[tid] = sum;
    __syncthreads();
    for (int s = 128; s > 0; s >>= 1) {
        if (tid < s) red[tid] += red[tid + s];
        __syncthreads();
    }
    if (tid == 0) s_inv = 1.0f / red[0];
    __syncthreads();

    float* attn = out + Bn * Dn;
    for (int l = tid; l < Ln; l += 256)
        attn[b * Ln + l] = expf(g_score[b * Ln + l] - s_max) * s_inv;
}

// ---------------------------------------------------------------------------
// context[b,d] = sum_l attn[b,l] * values_h[b,l,d]   (half2 path)
// ---------------------------------------------------------------------------
__global__ __launch_bounds__(512) void context_kernel(float* __restrict__ out)
{
    int lc = blockIdx.x;    // 16 chunks of 128 rows
    int b  = blockIdx.y;    // 32
    int d2 = threadIdx.x;   // 512 half2 cols
    const float* attn = out + Bn * Dn + b * Ln + lc * 128;
    const __half2* v = reinterpret_cast<const __half2*>(g_valsh)
                     + ((size_t)b * Ln + (size_t)lc * 128) * (Dn / 2) + d2;
    float ax = 0.f, ay = 0.f;
#pragma unroll 4
    for (int l = 0; l < 128; l++) {
        float2 f = __half22float2(v[(size_t)l * (Dn / 2)]);
        float w = __ldg(&attn[l]);
        ax += w * f.x;
        ay += w * f.y;
    }
    atomicAdd(&out[b * Dn + 2 * d2], ax);
    atomicAdd(&out[b * Dn + 2 * d2 + 1], ay);
}

// ---------------------------------------------------------------------------
extern "C" void kernel_launch(void* const* d_in, const int* in_sizes, int n_in,
                              void* d_out, int out_size)
{
    const float* query = (const float*)d_in[0];
    const float* values = (const float*)d_in[1];
    const float* mask = (const float*)d_in[2];
    const float* prev = (const float*)d_in[3];
    const int*   tstep = (const int*)d_in[4];
    const float* Wh = (const float*)d_in[5];
    const float* bh = (const float*)d_in[6];
    const float* Wv = (const float*)d_in[7];
    const float* bv = (const float*)d_in[8];
    const float* Wp = (const float*)d_in[9];
    const float* bp = (const float*)d_in[10];
    const float* Wm = (const float*)d_in[11];
    const float* bm = (const float*)d_in[12];
    const float* vw = (const float*)d_in[13];
    const float* vb = (const float*)d_in[14];
    float* out = (float*)d_out;

    const int smem_bytes = (NST * TM * KC + NST * TN * KC) * 2
                         + (8 * TN + TM + 8) * 4;
    cudaFuncSetAttribute(score_kernel,
                         cudaFuncAttributeMaxDynamicSharedMemorySize, smem_bytes);

    convert_values_kernel<<<((size_t)Bn * Ln * Dn / 8) / 256, 256>>>((const float4*)values);
    convert_wv_kernel<<<(Un * Dn) / 256, 256>>>(Wv);
    prep_kernel<<<Bn, 512>>>(query, mask, tstep, Wh, bh, bv, Wp, bp, bm);
    init_kernel<<<(Bn * Ln + 255) / 256, 256>>>(mask, vb, out);
    dim3 gs(Un / TN, Ln / TM, Bn);
    score_kernel<<<gs, 256, smem_bytes>>>(Wp, Wm, vw, prev);
    softmax_kernel<<<Bn, 256>>>(out);
    context_kernel<<<dim3(16, Bn), 512>>>(out);
}